// round 3
// baseline (speedup 1.0000x reference)
#include <cuda_runtime.h>

// Problem constants
#define TT  50
#define FF  24
#define H1  64
#define LAT 32
#define H3  64
#define BMAX 8192

typedef unsigned long long u64;

// Scratch (module-static device memory: allowed; no runtime allocation)
__device__ float g_h1[(size_t)BMAX * TT * H1];   // encoder LSTM1 sequences
__device__ float g_z [(size_t)BMAX * LAT];       // bottleneck latent

__device__ __forceinline__ float sigmoidf(float v) {
    return __fdividef(1.0f, 1.0f + __expf(-v));
}

// Packed dual-fp32 FMA (Blackwell f32x2 pipe; ptxas never auto-generates it)
__device__ __forceinline__ u64 ffma2(u64 a, u64 b, u64 c) {
    u64 d;
    asm("fma.rn.f32x2 %0, %1, %2, %3;" : "=l"(d) : "l"(a), "l"(b), "l"(c));
    return d;
}
__device__ __forceinline__ u64 pack2(float lo, float hi) {
    u64 r; asm("mov.b64 %0, {%1, %2};" : "=l"(r) : "f"(lo), "f"(hi)); return r;
}
__device__ __forceinline__ float2 unpack2(u64 v) {
    float2 f; asm("mov.b64 {%0, %1}, %2;" : "=f"(f.x), "=f"(f.y) : "l"(v)); return f;
}

// ---------------------------------------------------------------------------
// LSTM1: x[B,T,24] -> g_h1[B,T,64]
// 256 threads = 256 z-columns. Thread j keeps W1 col + U1 col packed in u64
// registers. R=8 batch rows per block.
// ---------------------------------------------------------------------------
__global__ void __launch_bounds__(256, 2) lstm1_kernel(
    const float* __restrict__ x, const float* __restrict__ W,
    const float* __restrict__ U, const float* __restrict__ b, int B)
{
    constexpr int D = FF, H = H1, G = 4 * H1, R = 8;
    __shared__ __align__(16) float xs[2][R][D];
    __shared__ __align__(16) float hs[R][H];
    __shared__ __align__(16) float zs[R][G];

    const int j    = threadIdx.x;
    const int row0 = blockIdx.x * R;

    u64 w2[D / 2], u2[H / 2];
#pragma unroll
    for (int k = 0; k < D / 2; k++) w2[k] = pack2(W[(2 * k) * G + j], W[(2 * k + 1) * G + j]);
#pragma unroll
    for (int k = 0; k < H / 2; k++) u2[k] = pack2(U[(2 * k) * G + j], U[(2 * k + 1) * G + j]);
    const float bj = b[j];
    const u64 binit = pack2(bj, 0.0f);

    for (int idx = j; idx < R * H; idx += 256) (&hs[0][0])[idx] = 0.0f;

    const int um = j & (H - 1);
    const int r0 = j >> 6;     // 0..3 -> rows r0 and r0+4
    float c0 = 0.0f, c1 = 0.0f;

    // x staging: R*D = 192 elements, one per thread j<192
    const int lr = j / D, lk = j - lr * D;
    float xreg = 0.0f;
    if (j < R * D) {
        int row = min(row0 + lr, B - 1);
        xreg = x[((size_t)row * TT + 0) * D + lk];
    }

    int buf = 0;
    for (int t = 0; t < TT; t++) {
        if (j < R * D) {
            xs[buf][lr][lk] = xreg;
            if (t + 1 < TT) {
                int row = min(row0 + lr, B - 1);
                xreg = x[((size_t)row * TT + (t + 1)) * D + lk];
            }
        }
        __syncthreads();   // A: xs[buf] + hs(t-1) visible

        u64 acc2[R];
#pragma unroll
        for (int r = 0; r < R; r++) acc2[r] = binit;
#pragma unroll
        for (int k = 0; k < D / 4; k++) {
#pragma unroll
            for (int r = 0; r < R; r++) {
                const ulonglong2 xv = *(const ulonglong2*)&xs[buf][r][4 * k];
                acc2[r] = ffma2(xv.x, w2[2 * k], acc2[r]);
                acc2[r] = ffma2(xv.y, w2[2 * k + 1], acc2[r]);
            }
        }
#pragma unroll
        for (int k = 0; k < H / 4; k++) {
#pragma unroll
            for (int r = 0; r < R; r++) {
                const ulonglong2 hv = *(const ulonglong2*)&hs[r][4 * k];
                acc2[r] = ffma2(hv.x, u2[2 * k], acc2[r]);
                acc2[r] = ffma2(hv.y, u2[2 * k + 1], acc2[r]);
            }
        }
#pragma unroll
        for (int r = 0; r < R; r++) {
            const float2 p = unpack2(acc2[r]);
            zs[r][j] = p.x + p.y;
        }
        __syncthreads();   // B: zs ready, hs reads done

        {
            float zi = zs[r0][um], zf = zs[r0][H + um];
            float zg = zs[r0][2 * H + um], zo = zs[r0][3 * H + um];
            c0 = sigmoidf(zf) * c0 + sigmoidf(zi) * fmaxf(zg, 0.0f);
            float hn = sigmoidf(zo) * fmaxf(c0, 0.0f);
            hs[r0][um] = hn;
            if (row0 + r0 < B) g_h1[((size_t)(row0 + r0) * TT + t) * H + um] = hn;
        }
        {
            const int r1 = r0 + 4;
            float zi = zs[r1][um], zf = zs[r1][H + um];
            float zg = zs[r1][2 * H + um], zo = zs[r1][3 * H + um];
            c1 = sigmoidf(zf) * c1 + sigmoidf(zi) * fmaxf(zg, 0.0f);
            float hn = sigmoidf(zo) * fmaxf(c1, 0.0f);
            hs[r1][um] = hn;
            if (row0 + r1 < B) g_h1[((size_t)(row0 + r1) * TT + t) * H + um] = hn;
        }
        buf ^= 1;
    }
}

// ---------------------------------------------------------------------------
// LSTM2: g_h1[B,T,64] -> g_z[B,32] (final h only)
// ---------------------------------------------------------------------------
__global__ void __launch_bounds__(128, 4) lstm2_kernel(
    const float* __restrict__ W, const float* __restrict__ U,
    const float* __restrict__ b, int B)
{
    constexpr int D = H1, H = LAT, G = 4 * LAT, R = 8;
    __shared__ __align__(16) float xs[2][R][D];
    __shared__ __align__(16) float hs[R][H];
    __shared__ __align__(16) float zs[R][G];

    const int j    = threadIdx.x;
    const int row0 = blockIdx.x * R;

    u64 w2[D / 2], u2[H / 2];
#pragma unroll
    for (int k = 0; k < D / 2; k++) w2[k] = pack2(W[(2 * k) * G + j], W[(2 * k + 1) * G + j]);
#pragma unroll
    for (int k = 0; k < H / 2; k++) u2[k] = pack2(U[(2 * k) * G + j], U[(2 * k + 1) * G + j]);
    const float bj = b[j];
    const u64 binit = pack2(bj, 0.0f);

    for (int idx = j; idx < R * H; idx += 128) (&hs[0][0])[idx] = 0.0f;

    const int um = j & (H - 1);
    const int r0 = j >> 5;     // 0..3 -> rows r0 and r0+4
    float c0 = 0.0f, c1 = 0.0f;

    // staging: R*D = 512 floats, float4 per thread
    const int lr = j >> 4, lk = (j & 15) * 4;
    float4 xreg;
    {
        int row = min(row0 + lr, B - 1);
        xreg = *(const float4*)&g_h1[((size_t)row * TT + 0) * D + lk];
    }

    int buf = 0;
    for (int t = 0; t < TT; t++) {
        *(float4*)&xs[buf][lr][lk] = xreg;
        if (t + 1 < TT) {
            int row = min(row0 + lr, B - 1);
            xreg = *(const float4*)&g_h1[((size_t)row * TT + (t + 1)) * D + lk];
        }
        __syncthreads();   // A

        u64 acc2[R];
#pragma unroll
        for (int r = 0; r < R; r++) acc2[r] = binit;
#pragma unroll
        for (int k = 0; k < D / 4; k++) {
#pragma unroll
            for (int r = 0; r < R; r++) {
                const ulonglong2 xv = *(const ulonglong2*)&xs[buf][r][4 * k];
                acc2[r] = ffma2(xv.x, w2[2 * k], acc2[r]);
                acc2[r] = ffma2(xv.y, w2[2 * k + 1], acc2[r]);
            }
        }
#pragma unroll
        for (int k = 0; k < H / 4; k++) {
#pragma unroll
            for (int r = 0; r < R; r++) {
                const ulonglong2 hv = *(const ulonglong2*)&hs[r][4 * k];
                acc2[r] = ffma2(hv.x, u2[2 * k], acc2[r]);
                acc2[r] = ffma2(hv.y, u2[2 * k + 1], acc2[r]);
            }
        }
#pragma unroll
        for (int r = 0; r < R; r++) {
            const float2 p = unpack2(acc2[r]);
            zs[r][j] = p.x + p.y;
        }
        __syncthreads();   // B

        {
            float zi = zs[r0][um], zf = zs[r0][H + um];
            float zg = zs[r0][2 * H + um], zo = zs[r0][3 * H + um];
            c0 = sigmoidf(zf) * c0 + sigmoidf(zi) * fmaxf(zg, 0.0f);
            float hn = sigmoidf(zo) * fmaxf(c0, 0.0f);
            hs[r0][um] = hn;
            if (t == TT - 1 && row0 + r0 < B) g_z[(size_t)(row0 + r0) * H + um] = hn;
        }
        {
            const int r1 = r0 + 4;
            float zi = zs[r1][um], zf = zs[r1][H + um];
            float zg = zs[r1][2 * H + um], zo = zs[r1][3 * H + um];
            c1 = sigmoidf(zf) * c1 + sigmoidf(zi) * fmaxf(zg, 0.0f);
            float hn = sigmoidf(zo) * fmaxf(c1, 0.0f);
            hs[r1][um] = hn;
            if (t == TT - 1 && row0 + r1 < B) g_z[(size_t)(row0 + r1) * H + um] = hn;
        }
        buf ^= 1;
    }
}

// ---------------------------------------------------------------------------
// LSTM3 + TimeDistributed Dense: g_z[B,32] (RepeatVector) -> out[B,T,24]
// ---------------------------------------------------------------------------
__global__ void __launch_bounds__(256, 2) lstm3_kernel(
    const float* __restrict__ W, const float* __restrict__ U,
    const float* __restrict__ b, const float* __restrict__ Wd,
    const float* __restrict__ bd, float* __restrict__ out, int B)
{
    constexpr int D = LAT, H = H3, G = 4 * H3, R = 8;
    constexpr int WDP = 68;              // padded row for transposed Wd (272B = 17*16B)
    __shared__ __align__(16) float zin[R][D];
    __shared__ __align__(16) float hs[R][H];
    __shared__ __align__(16) float zb[R][G];
    __shared__ __align__(16) float wdst[FF][WDP];   // wdst[f][h] = Wd[h][f]

    const int j    = threadIdx.x;
    const int row0 = blockIdx.x * R;

    u64 u2[H / 2];
#pragma unroll
    for (int k = 0; k < H / 2; k++) u2[k] = pack2(U[(2 * k) * G + j], U[(2 * k + 1) * G + j]);

    // load transposed Wd
    for (int idx = j; idx < H * FF; idx += 256) {
        int h = idx / FF, f = idx - h * FF;
        wdst[f][h] = Wd[idx];
    }
    // load latent z: R*32 = 256 == blockDim
    {
        int r = j >> 5, k = j & 31;
        int row = min(row0 + r, B - 1);
        zin[r][k] = g_z[(size_t)row * D + k];
    }
    for (int idx = j; idx < R * H; idx += 256) (&hs[0][0])[idx] = 0.0f;
    __syncthreads();

    // precompute zw[r] = b[j] + sum_k z[r][k] * W3[k][j]  (input constant over t)
    const float bj = b[j];
    float zw[R];
    {
        u64 w2[D / 2];
#pragma unroll
        for (int k = 0; k < D / 2; k++) w2[k] = pack2(W[(2 * k) * G + j], W[(2 * k + 1) * G + j]);
        u64 zacc[R];
#pragma unroll
        for (int r = 0; r < R; r++) zacc[r] = pack2(bj, 0.0f);
#pragma unroll
        for (int k = 0; k < D / 2; k++) {
#pragma unroll
            for (int r = 0; r < R; r++) {
                const u64 zv = *(const u64*)&zin[r][2 * k];
                zacc[r] = ffma2(zv, w2[k], zacc[r]);
            }
        }
#pragma unroll
        for (int r = 0; r < R; r++) {
            const float2 p = unpack2(zacc[r]);
            zw[r] = p.x + p.y;
        }
    }

    const int um = j & (H - 1);
    const int r0 = j >> 6;
    float c0 = 0.0f, c1 = 0.0f;

    const int df = j % FF, dr = j / FF;  // dense task (j < 192)
    const float bdf = (j < R * FF) ? bd[df] : 0.0f;
    const u64 dinit = pack2(bdf, 0.0f);

    for (int t = 0; t < TT; t++) {
        u64 acc2[R];
#pragma unroll
        for (int r = 0; r < R; r++) acc2[r] = pack2(zw[r], 0.0f);
#pragma unroll
        for (int k = 0; k < H / 4; k++) {
#pragma unroll
            for (int r = 0; r < R; r++) {
                const ulonglong2 hv = *(const ulonglong2*)&hs[r][4 * k];
                acc2[r] = ffma2(hv.x, u2[2 * k], acc2[r]);
                acc2[r] = ffma2(hv.y, u2[2 * k + 1], acc2[r]);
            }
        }
#pragma unroll
        for (int r = 0; r < R; r++) {
            const float2 p = unpack2(acc2[r]);
            zb[r][j] = p.x + p.y;
        }
        __syncthreads();   // S2: zb ready, hs reads done

        {
            float zi = zb[r0][um], zf = zb[r0][H + um];
            float zg = zb[r0][2 * H + um], zo = zb[r0][3 * H + um];
            c0 = sigmoidf(zf) * c0 + sigmoidf(zi) * fmaxf(zg, 0.0f);
            float hn = sigmoidf(zo) * fmaxf(c0, 0.0f);
            hs[r0][um] = hn;
        }
        {
            const int r1 = r0 + 4;
            float zi = zb[r1][um], zf = zb[r1][H + um];
            float zg = zb[r1][2 * H + um], zo = zb[r1][3 * H + um];
            c1 = sigmoidf(zf) * c1 + sigmoidf(zi) * fmaxf(zg, 0.0f);
            float hn = sigmoidf(zo) * fmaxf(c1, 0.0f);
            hs[r1][um] = hn;
        }
        __syncthreads();   // S3: hs(t) visible

        if (j < R * FF) {
            int row = row0 + dr;
            if (row < B) {
                u64 sacc = dinit;
#pragma unroll
                for (int k = 0; k < H / 4; k++) {
                    const ulonglong2 hv = *(const ulonglong2*)&hs[dr][4 * k];
                    const ulonglong2 wv = *(const ulonglong2*)&wdst[df][4 * k];
                    sacc = ffma2(hv.x, wv.x, sacc);
                    sacc = ffma2(hv.y, wv.y, sacc);
                }
                const float2 p = unpack2(sacc);
                out[((size_t)row * TT + t) * FF + df] = p.x + p.y;
            }
        }
    }
}

// ---------------------------------------------------------------------------
extern "C" void kernel_launch(void* const* d_in, const int* in_sizes, int n_in,
                              void* d_out, int out_size)
{
    const float* x  = (const float*)d_in[0];
    const float* W1 = (const float*)d_in[1];
    const float* U1 = (const float*)d_in[2];
    const float* b1 = (const float*)d_in[3];
    const float* W2 = (const float*)d_in[4];
    const float* U2 = (const float*)d_in[5];
    const float* b2 = (const float*)d_in[6];
    const float* W3 = (const float*)d_in[7];
    const float* U3 = (const float*)d_in[8];
    const float* b3 = (const float*)d_in[9];
    const float* Wd = (const float*)d_in[10];
    const float* bd = (const float*)d_in[11];
    float* out = (float*)d_out;

    const int B = in_sizes[0] / (TT * FF);
    const int nblk = (B + 7) / 8;

    lstm1_kernel<<<nblk, 256>>>(x, W1, U1, b1, B);
    lstm2_kernel<<<nblk, 128>>>(W2, U2, b2, B);
    lstm3_kernel<<<nblk, 256>>>(W3, U3, b3, Wd, bd, out, B);
}

// round 5
// speedup vs baseline: 1.3644x; 1.3644x over previous
#include <cuda_runtime.h>
#include <cstdint>

#define TT  50
#define FF  24
#define H1  64
#define LAT 32
#define H3  64
#define BMAX 8192

typedef unsigned long long u64;

__device__ float g_h1[(size_t)BMAX * TT * H1];   // [B][T][64]
__device__ float g_z [(size_t)BMAX * LAT];

__device__ __forceinline__ float sigmoidf(float v) {
    return __fdividef(1.0f, 1.0f + __expf(-v));
}
__device__ __forceinline__ u64 ffma2(u64 a, u64 b, u64 c) {
    u64 d; asm("fma.rn.f32x2 %0, %1, %2, %3;" : "=l"(d) : "l"(a), "l"(b), "l"(c)); return d;
}
__device__ __forceinline__ u64 pack2(float lo, float hi) {
    u64 r; asm("mov.b64 %0, {%1, %2};" : "=l"(r) : "f"(lo), "f"(hi)); return r;
}
__device__ __forceinline__ float2 unpack2(u64 v) {
    float2 f; asm("mov.b64 {%0, %1}, %2;" : "=f"(f.x), "=f"(f.y) : "l"(v)); return f;
}

// ---------------------------------------------------------------------------
// LSTM1: x[B,T,24] -> g_h1[B,T,64]
// 128 threads, C=2 columns per thread (cols 2j, 2j+1), R=8 rows per block.
// Each LDS.128 of activations feeds 8 FMAs (2 cols) -> LDS traffic halved.
// ---------------------------------------------------------------------------
__global__ void __launch_bounds__(128, 2) lstm1_kernel(
    const float* __restrict__ x, const float* __restrict__ W,
    const float* __restrict__ U, const float* __restrict__ b, int B)
{
    constexpr int D = FF, H = H1, G = 4 * H1, R = 8;
    __shared__ __align__(16) float xs[2][R][D];
    __shared__ __align__(16) float hs[R][H];
    __shared__ __align__(16) float zs[R][G];

    const int j    = threadIdx.x;
    const int cA   = 2 * j, cB = 2 * j + 1;
    const int row0 = blockIdx.x * R;

    u64 wA[D / 2], wB[D / 2], uA[H / 2], uB[H / 2];
#pragma unroll
    for (int k = 0; k < D / 2; k++) {
        wA[k] = pack2(W[(2 * k) * G + cA], W[(2 * k + 1) * G + cA]);
        wB[k] = pack2(W[(2 * k) * G + cB], W[(2 * k + 1) * G + cB]);
    }
#pragma unroll
    for (int k = 0; k < H / 2; k++) {
        uA[k] = pack2(U[(2 * k) * G + cA], U[(2 * k + 1) * G + cA]);
        uB[k] = pack2(U[(2 * k) * G + cB], U[(2 * k + 1) * G + cB]);
    }
    const u64 bA = pack2(b[cA], 0.0f);
    const u64 bB = pack2(b[cB], 0.0f);

    for (int idx = j; idx < R * H; idx += 128) (&hs[0][0])[idx] = 0.0f;

    // gate tasks: 4 per thread. um = j&63, rows rbase+2q.
    const int um = j & (H - 1);
    const int rbase = j >> 6;          // 0..1
    float cst[4] = {0.0f, 0.0f, 0.0f, 0.0f};

    // x staging: 192 elements; thread j loads idx j and (j<64) idx j+128
    const int i0 = j, i1 = j + 128;
    const int lr0 = i0 / D, lk0 = i0 - lr0 * D;
    const int lr1 = i1 / D, lk1 = i1 - lr1 * D;
    float xr0 = 0.0f, xr1 = 0.0f;
    {
        int r0c = min(row0 + lr0, B - 1);
        xr0 = x[((size_t)r0c * TT + 0) * D + lk0];
        if (j < 64) {
            int r1c = min(row0 + lr1, B - 1);
            xr1 = x[((size_t)r1c * TT + 0) * D + lk1];
        }
    }

    int buf = 0;
    for (int t = 0; t < TT; t++) {
        xs[buf][lr0][lk0] = xr0;
        if (j < 64) xs[buf][lr1][lk1] = xr1;
        if (t + 1 < TT) {
            int r0c = min(row0 + lr0, B - 1);
            xr0 = x[((size_t)r0c * TT + (t + 1)) * D + lk0];
            if (j < 64) {
                int r1c = min(row0 + lr1, B - 1);
                xr1 = x[((size_t)r1c * TT + (t + 1)) * D + lk1];
            }
        }
        __syncthreads();   // A: xs + hs(t-1) visible

        u64 accA[R], accB[R];
#pragma unroll
        for (int r = 0; r < R; r++) { accA[r] = bA; accB[r] = bB; }
#pragma unroll
        for (int k = 0; k < D / 4; k++) {
#pragma unroll
            for (int r = 0; r < R; r++) {
                const ulonglong2 xv = *(const ulonglong2*)&xs[buf][r][4 * k];
                accA[r] = ffma2(xv.x, wA[2 * k], accA[r]);
                accA[r] = ffma2(xv.y, wA[2 * k + 1], accA[r]);
                accB[r] = ffma2(xv.x, wB[2 * k], accB[r]);
                accB[r] = ffma2(xv.y, wB[2 * k + 1], accB[r]);
            }
        }
#pragma unroll
        for (int k = 0; k < H / 4; k++) {
#pragma unroll
            for (int r = 0; r < R; r++) {
                const ulonglong2 hv = *(const ulonglong2*)&hs[r][4 * k];
                accA[r] = ffma2(hv.x, uA[2 * k], accA[r]);
                accA[r] = ffma2(hv.y, uA[2 * k + 1], accA[r]);
                accB[r] = ffma2(hv.x, uB[2 * k], accB[r]);
                accB[r] = ffma2(hv.y, uB[2 * k + 1], accB[r]);
            }
        }
#pragma unroll
        for (int r = 0; r < R; r++) {
            const float2 pA = unpack2(accA[r]);
            const float2 pB = unpack2(accB[r]);
            *(float2*)&zs[r][cA] = make_float2(pA.x + pA.y, pB.x + pB.y);
        }
        __syncthreads();   // B: zs ready, hs reads done

#pragma unroll
        for (int q = 0; q < 4; q++) {
            const int r = rbase + 2 * q;
            float zi = zs[r][um], zf = zs[r][H + um];
            float zg = zs[r][2 * H + um], zo = zs[r][3 * H + um];
            cst[q] = sigmoidf(zf) * cst[q] + sigmoidf(zi) * fmaxf(zg, 0.0f);
            float hn = sigmoidf(zo) * fmaxf(cst[q], 0.0f);
            hs[r][um] = hn;
            if (row0 + r < B) g_h1[((size_t)(row0 + r) * TT + t) * H + um] = hn;
        }
        buf ^= 1;
    }
}

// ---------------------------------------------------------------------------
// LSTM2: g_h1[B,T,64] -> g_z[B,32]. 64 threads, C=2, R=8.
// ---------------------------------------------------------------------------
__global__ void __launch_bounds__(64, 4) lstm2_kernel(
    const float* __restrict__ W, const float* __restrict__ U,
    const float* __restrict__ b, int B)
{
    constexpr int D = H1, H = LAT, G = 4 * LAT, R = 8;
    __shared__ __align__(16) float xs[2][R][D];
    __shared__ __align__(16) float hs[R][H];
    __shared__ __align__(16) float zs[R][G];

    const int j    = threadIdx.x;
    const int cA   = 2 * j, cB = 2 * j + 1;
    const int row0 = blockIdx.x * R;

    u64 wA[D / 2], wB[D / 2], uA[H / 2], uB[H / 2];
#pragma unroll
    for (int k = 0; k < D / 2; k++) {
        wA[k] = pack2(W[(2 * k) * G + cA], W[(2 * k + 1) * G + cA]);
        wB[k] = pack2(W[(2 * k) * G + cB], W[(2 * k + 1) * G + cB]);
    }
#pragma unroll
    for (int k = 0; k < H / 2; k++) {
        uA[k] = pack2(U[(2 * k) * G + cA], U[(2 * k + 1) * G + cA]);
        uB[k] = pack2(U[(2 * k) * G + cB], U[(2 * k + 1) * G + cB]);
    }
    const u64 bA = pack2(b[cA], 0.0f);
    const u64 bB = pack2(b[cB], 0.0f);

    for (int idx = j; idx < R * H; idx += 64) (&hs[0][0])[idx] = 0.0f;

    const int um = j & (H - 1);
    const int rbase = j >> 5;          // 0..1
    float cst[4] = {0.0f, 0.0f, 0.0f, 0.0f};

    // staging: 512 floats / 64 threads = 8 each (2x float4)
    const int lr = j >> 3, lk = (j & 7) * 8;
    float4 xg0, xg1;
    {
        int row = min(row0 + lr, B - 1);
        const float4* p = (const float4*)&g_h1[((size_t)row * TT + 0) * D + lk];
        xg0 = p[0]; xg1 = p[1];
    }

    int buf = 0;
    for (int t = 0; t < TT; t++) {
        *(float4*)&xs[buf][lr][lk]     = xg0;
        *(float4*)&xs[buf][lr][lk + 4] = xg1;
        if (t + 1 < TT) {
            int row = min(row0 + lr, B - 1);
            const float4* p = (const float4*)&g_h1[((size_t)row * TT + (t + 1)) * D + lk];
            xg0 = p[0]; xg1 = p[1];
        }
        __syncthreads();

        u64 accA[R], accB[R];
#pragma unroll
        for (int r = 0; r < R; r++) { accA[r] = bA; accB[r] = bB; }
#pragma unroll
        for (int k = 0; k < D / 4; k++) {
#pragma unroll
            for (int r = 0; r < R; r++) {
                const ulonglong2 xv = *(const ulonglong2*)&xs[buf][r][4 * k];
                accA[r] = ffma2(xv.x, wA[2 * k], accA[r]);
                accA[r] = ffma2(xv.y, wA[2 * k + 1], accA[r]);
                accB[r] = ffma2(xv.x, wB[2 * k], accB[r]);
                accB[r] = ffma2(xv.y, wB[2 * k + 1], accB[r]);
            }
        }
#pragma unroll
        for (int k = 0; k < H / 4; k++) {
#pragma unroll
            for (int r = 0; r < R; r++) {
                const ulonglong2 hv = *(const ulonglong2*)&hs[r][4 * k];
                accA[r] = ffma2(hv.x, uA[2 * k], accA[r]);
                accA[r] = ffma2(hv.y, uA[2 * k + 1], accA[r]);
                accB[r] = ffma2(hv.x, uB[2 * k], accB[r]);
                accB[r] = ffma2(hv.y, uB[2 * k + 1], accB[r]);
            }
        }
#pragma unroll
        for (int r = 0; r < R; r++) {
            const float2 pA = unpack2(accA[r]);
            const float2 pB = unpack2(accB[r]);
            *(float2*)&zs[r][cA] = make_float2(pA.x + pA.y, pB.x + pB.y);
        }
        __syncthreads();

#pragma unroll
        for (int q = 0; q < 4; q++) {
            const int r = rbase + 2 * q;
            float zi = zs[r][um], zf = zs[r][H + um];
            float zg = zs[r][2 * H + um], zo = zs[r][3 * H + um];
            cst[q] = sigmoidf(zf) * cst[q] + sigmoidf(zi) * fmaxf(zg, 0.0f);
            float hn = sigmoidf(zo) * fmaxf(cst[q], 0.0f);
            hs[r][um] = hn;
            if (t == TT - 1 && row0 + r < B) g_z[(size_t)(row0 + r) * H + um] = hn;
        }
        buf ^= 1;
    }
}

// ---------------------------------------------------------------------------
// LSTM3 + TimeDistributed Dense: g_z[B,32] -> out[B,T,24]. 128 threads, C=2.
// ---------------------------------------------------------------------------
__global__ void __launch_bounds__(128, 2) lstm3_kernel(
    const float* __restrict__ W, const float* __restrict__ U,
    const float* __restrict__ b, const float* __restrict__ Wd,
    const float* __restrict__ bd, float* __restrict__ out, int B)
{
    constexpr int D = LAT, H = H3, G = 4 * H3, R = 8;
    constexpr int WDP = 68;
    __shared__ __align__(16) float zin[R][D];
    __shared__ __align__(16) float hs[R][H];
    __shared__ __align__(16) float zb[R][G];
    __shared__ __align__(16) float wdst[FF][WDP];

    const int j    = threadIdx.x;
    const int cA   = 2 * j, cB = 2 * j + 1;
    const int row0 = blockIdx.x * R;

    u64 uA[H / 2], uB[H / 2];
#pragma unroll
    for (int k = 0; k < H / 2; k++) {
        uA[k] = pack2(U[(2 * k) * G + cA], U[(2 * k + 1) * G + cA]);
        uB[k] = pack2(U[(2 * k) * G + cB], U[(2 * k + 1) * G + cB]);
    }

    for (int idx = j; idx < H * FF; idx += 128) {
        int h = idx / FF, f = idx - h * FF;
        wdst[f][h] = Wd[idx];
    }
    for (int idx = j; idx < R * D; idx += 128) {
        int r = idx >> 5, k = idx & 31;
        int row = min(row0 + r, B - 1);
        zin[r][k] = g_z[(size_t)row * D + k];
    }
    for (int idx = j; idx < R * H; idx += 128) (&hs[0][0])[idx] = 0.0f;
    __syncthreads();

    // zw precompute (input constant over t): per col
    float zwA[R], zwB[R];
    {
        const float bvA = b[cA], bvB = b[cB];
#pragma unroll
        for (int r = 0; r < R; r++) { zwA[r] = bvA; zwB[r] = bvB; }
        for (int k = 0; k < D; k++) {
            const float wkA = W[k * G + cA], wkB = W[k * G + cB];
#pragma unroll
            for (int r = 0; r < R; r++) {
                zwA[r] += zin[r][k] * wkA;
                zwB[r] += zin[r][k] * wkB;
            }
        }
    }

    const int um = j & (H - 1);
    const int rbase = j >> 6;
    float cst[4] = {0.0f, 0.0f, 0.0f, 0.0f};

    // dense tasks: 192 over 128 threads: task j, and j+128 (j<64)
    const int d0f = j % FF, d0r = j / FF;
    const int d1f = (j + 128) % FF, d1r = (j + 128) / FF;
    const float bd0 = bd[d0f];
    const float bd1 = (j < 64) ? bd[d1f] : 0.0f;

    for (int t = 0; t < TT; t++) {
        u64 accA[R], accB[R];
#pragma unroll
        for (int r = 0; r < R; r++) {
            accA[r] = pack2(zwA[r], 0.0f);
            accB[r] = pack2(zwB[r], 0.0f);
        }
#pragma unroll
        for (int k = 0; k < H / 4; k++) {
#pragma unroll
            for (int r = 0; r < R; r++) {
                const ulonglong2 hv = *(const ulonglong2*)&hs[r][4 * k];
                accA[r] = ffma2(hv.x, uA[2 * k], accA[r]);
                accA[r] = ffma2(hv.y, uA[2 * k + 1], accA[r]);
                accB[r] = ffma2(hv.x, uB[2 * k], accB[r]);
                accB[r] = ffma2(hv.y, uB[2 * k + 1], accB[r]);
            }
        }
#pragma unroll
        for (int r = 0; r < R; r++) {
            const float2 pA = unpack2(accA[r]);
            const float2 pB = unpack2(accB[r]);
            *(float2*)&zb[r][cA] = make_float2(pA.x + pA.y, pB.x + pB.y);
        }
        __syncthreads();   // S2: zb ready, hs reads done

#pragma unroll
        for (int q = 0; q < 4; q++) {
            const int r = rbase + 2 * q;
            float zi = zb[r][um], zf = zb[r][H + um];
            float zg = zb[r][2 * H + um], zo = zb[r][3 * H + um];
            cst[q] = sigmoidf(zf) * cst[q] + sigmoidf(zi) * fmaxf(zg, 0.0f);
            float hn = sigmoidf(zo) * fmaxf(cst[q], 0.0f);
            hs[r][um] = hn;
        }
        __syncthreads();   // S3: hs(t) visible

        // dense
        {
            int row = row0 + d0r;
            if (row < B) {
                u64 sacc = pack2(bd0, 0.0f);
#pragma unroll
                for (int k = 0; k < H / 4; k++) {
                    const ulonglong2 hv = *(const ulonglong2*)&hs[d0r][4 * k];
                    const ulonglong2 wv = *(const ulonglong2*)&wdst[d0f][4 * k];
                    sacc = ffma2(hv.x, wv.x, sacc);
                    sacc = ffma2(hv.y, wv.y, sacc);
                }
                const float2 p = unpack2(sacc);
                out[((size_t)row * TT + t) * FF + d0f] = p.x + p.y;
            }
        }
        if (j < 64) {
            int row = row0 + d1r;
            if (row < B) {
                u64 sacc = pack2(bd1, 0.0f);
#pragma unroll
                for (int k = 0; k < H / 4; k++) {
                    const ulonglong2 hv = *(const ulonglong2*)&hs[d1r][4 * k];
                    const ulonglong2 wv = *(const ulonglong2*)&wdst[d1f][4 * k];
                    sacc = ffma2(hv.x, wv.x, sacc);
                    sacc = ffma2(hv.y, wv.y, sacc);
                }
                const float2 p = unpack2(sacc);
                out[((size_t)row * TT + t) * FF + d1f] = p.x + p.y;
            }
        }
    }
}

// ---------------------------------------------------------------------------
extern "C" void kernel_launch(void* const* d_in, const int* in_sizes, int n_in,
                              void* d_out, int out_size)
{
    const float* x  = (const float*)d_in[0];
    const float* W1 = (const float*)d_in[1];
    const float* U1 = (const float*)d_in[2];
    const float* b1 = (const float*)d_in[3];
    const float* W2 = (const float*)d_in[4];
    const float* U2 = (const float*)d_in[5];
    const float* b2 = (const float*)d_in[6];
    const float* W3 = (const float*)d_in[7];
    const float* U3 = (const float*)d_in[8];
    const float* b3 = (const float*)d_in[9];
    const float* Wd = (const float*)d_in[10];
    const float* bd = (const float*)d_in[11];
    float* out = (float*)d_out;

    const int B = in_sizes[0] / (TT * FF);
    const int nblk = (B + 7) / 8;

    lstm1_kernel<<<nblk, 128>>>(x, W1, U1, b1, B);
    lstm2_kernel<<<nblk, 64>>>(W2, U2, b2, B);
    lstm3_kernel<<<nblk, 128>>>(W3, U3, b3, Wd, bd, out, B);
}